// round 16
// baseline (speedup 1.0000x reference)
#include <cuda_runtime.h>
#include <math.h>
#include <stdint.h>

#define CIN  256
#define COUT 256
#define HH   64
#define WW   64
#define BB   4
#define DGRP 2
#define CG   128
#define KK2  9
#define NTAP 18
#define NPIX 4096   // 64*64

// ---------------- scratch (device globals; no allocations allowed) ----------------
__device__ float g_xt[BB * NPIX * CIN];                       // x -> [B][H*W][C]
__device__ float g_om[BB * NPIX * 54];                        // offset-conv out [b][p][54]
// main w, per (tap, k-chunk): [hi 32KB][lo 32KB]; tile = 256 o-rows x 64 c bf16, 128B pitch, swizzled
__device__ __align__(128) unsigned char g_wbf[NTAP * 131072];
__device__ __align__(128) unsigned char g_woffbf[KK2 * 2 * 32768]; // w_off: per (k2,half) [hi 16KB][lo 16KB]

// ---------------- bf16 helpers ----------------
// packbf(vlo, vhi): vlo -> low 16 bits, vhi -> high 16 bits
static __device__ __forceinline__ uint32_t packbf(float vlo, float vhi) {
    uint32_t r;
    asm("cvt.rn.bf16x2.f32 %0, %1, %2;" : "=r"(r) : "f"(vhi), "f"(vlo));
    return r;
}
static __device__ __forceinline__ float bflo(uint32_t w) { return __uint_as_float(w << 16); }
static __device__ __forceinline__ float bfhi(uint32_t w) { return __uint_as_float(w & 0xffff0000u); }

static __device__ __forceinline__ uint32_t smem_u32(const void* p) {
    uint32_t a;
    asm("{ .reg .u64 t; cvta.to.shared.u64 t, %1; cvt.u32.u64 %0, t; }" : "=r"(a) : "l"(p));
    return a;
}

// ---------------- mma.sync / ldmatrix (base-arch PTX, HMMA pipe) ----------------
static __device__ __forceinline__ void ldsm4(uint32_t& r0, uint32_t& r1,
                                             uint32_t& r2, uint32_t& r3, uint32_t a) {
    asm volatile("ldmatrix.sync.aligned.m8n8.x4.shared.b16 {%0,%1,%2,%3}, [%4];"
                 : "=r"(r0), "=r"(r1), "=r"(r2), "=r"(r3) : "r"(a));
}
static __device__ __forceinline__ void mma16816(float* c, const uint32_t* a,
                                                uint32_t b0, uint32_t b1) {
    asm volatile(
        "mma.sync.aligned.m16n8k16.row.col.f32.bf16.bf16.f32 "
        "{%0,%1,%2,%3}, {%4,%5,%6,%7}, {%8,%9}, {%0,%1,%2,%3};"
        : "+f"(c[0]), "+f"(c[1]), "+f"(c[2]), "+f"(c[3])
        : "r"(a[0]), "r"(a[1]), "r"(a[2]), "r"(a[3]), "r"(b0), "r"(b1));
}

// ---------------- kernel 0: x [B,C,H,W] -> g_xt [B,HW,C] ----------------
__global__ void k_transpose_x(const float* __restrict__ x) {
    __shared__ float tile[32][33];
    int b  = blockIdx.z;
    int p0 = blockIdx.x * 32;
    int c0 = blockIdx.y * 32;
    #pragma unroll
    for (int k = 0; k < 32; k += 8)
        tile[threadIdx.y + k][threadIdx.x] = x[(b * CIN + c0 + threadIdx.y + k) * NPIX + p0 + threadIdx.x];
    __syncthreads();
    #pragma unroll
    for (int k = 0; k < 32; k += 8)
        g_xt[(b * NPIX + p0 + threadIdx.y + k) * CIN + c0 + threadIdx.x] = tile[threadIdx.x][threadIdx.y + k];
}

// ---------------- kernel 1: w -> g_wbf (bf16 hi/lo, chunked swizzled tiles) ----------------
// per (tap, chunk): 256 o-rows x 64 c, row pitch 128B, swizzle byte = cin*2 ^ ((o&7)<<4)
__global__ void k_prep_wbf(const float* __restrict__ w) {
    int tid = blockIdx.x * blockDim.x + threadIdx.x;
    if (tid >= NTAP * 256 * 64) return;
    int cp  = tid & 63;             // c pair index: c0 = 2*cp (0..126)
    int o   = (tid >> 6) & 255;
    int tap = tid >> 14;
    int g = tap / KK2, k2 = tap % KK2;
    int c0 = cp * 2;
    int chunk = c0 >> 6;            // which 64-c half
    int cin   = c0 & 63;            // c within chunk
    float f0 = w[((size_t)o * CIN + g * CG + c0) * KK2 + k2];
    float f1 = w[((size_t)o * CIN + g * CG + c0 + 1) * KK2 + k2];
    uint32_t hiw = packbf(f0, f1);
    float r0 = f0 - bflo(hiw);
    float r1 = f1 - bfhi(hiw);
    uint32_t low = packbf(r0, r1);
    uint32_t sw = (uint32_t)o * 128 + (((uint32_t)cin * 2) ^ (((uint32_t)(o & 7)) << 4));
    size_t base = (size_t)tap * 131072 + (size_t)chunk * 65536;
    *(uint32_t*)(g_wbf + base + sw)         = hiw;
    *(uint32_t*)(g_wbf + base + 32768 + sw) = low;
}

// ---------------- kernel 2: w_off -> g_woffbf bf16 hi/lo tiles [k2][half]: 64 oc x 128 c ----------------
__global__ void k_prep_woffbf(const float* __restrict__ w_off) {
    int tid = blockIdx.x * blockDim.x + threadIdx.x;
    if (tid >= KK2 * 2 * 64 * 64) return;
    int cp   = tid & 63;            // c pair: c0 = 2*cp within half
    int o    = (tid >> 6) & 63;     // oc row (pad >=54 with 0)
    int half = (tid >> 12) & 1;
    int k2   = tid >> 13;           // 0..8
    int c0 = cp * 2;
    float f0 = 0.f, f1 = 0.f;
    if (o < 54) {
        f0 = w_off[((size_t)o * CIN + half * 128 + c0) * KK2 + k2];
        f1 = w_off[((size_t)o * CIN + half * 128 + c0 + 1) * KK2 + k2];
    }
    uint32_t hiw = packbf(f0, f1);
    float r0 = f0 - bflo(hiw);
    float r1 = f1 - bfhi(hiw);
    uint32_t low = packbf(r0, r1);
    uint32_t sw = (uint32_t)o * 256 + (((uint32_t)c0 * 2) ^ (((uint32_t)(o & 7)) << 4));
    size_t base = (size_t)(k2 * 2 + half) * 32768;
    *(uint32_t*)(g_woffbf + base + sw)         = hiw;
    *(uint32_t*)(g_woffbf + base + 16384 + sw) = low;
}

// ---------------- kernel 3: offset conv via mma.sync bf16x3 (round-14 best shape) ----------------
// block = 256 thr (8 warps), tile = 64 pix x 64 oc(pad); warp = 16 pix x 32 oc
// smem: A hi 16KB | A lo 16KB | B hi 16KB | B lo 16KB = 64KB
#define OA_HI 0
#define OA_LO 16384
#define OB_HI 32768
#define OB_LO 49152
#define OSMEM_SZ 65536

__global__ void __launch_bounds__(256, 2) k_offset_mma(const float* __restrict__ b_off) {
    extern __shared__ char dsm[];
    uint32_t sb = smem_u32(dsm);
    int tid = threadIdx.x;
    int lane = tid & 31, wid = tid >> 5;

    int b     = blockIdx.x >> 6;
    int ptile = blockIdx.x & 63;
    int p0    = ptile << 6;          // 64 pixels = one image row

    int pix0 = (wid & 3) * 16;       // warp pixel sub-tile
    int o0   = (wid >> 2) * 32;      // warp oc sub-tile

    // ldmatrix lane geometry
    int rowA = lane & 15;
    uint32_t cA  = (uint32_t)((lane >> 4) << 4);
    int rowB = (lane & 7) + ((lane >> 4) << 3);
    uint32_t cB  = (uint32_t)(((lane >> 3) & 1) << 4);
    uint32_t swz = (uint32_t)((lane & 7) << 4);

    uint32_t aRow = sb + OA_HI + (uint32_t)(pix0 + rowA) * 256;
    uint32_t bRow[2];
    #pragma unroll
    for (int ng = 0; ng < 2; ng++)
        bRow[ng] = sb + OB_HI + (uint32_t)(o0 + ng * 16 + rowB) * 256;

    float acc[4][4];
    #pragma unroll
    for (int nt = 0; nt < 4; nt++)
        #pragma unroll
        for (int q = 0; q < 4; q++) acc[nt][q] = 0.f;

    const float* xb = g_xt + (size_t)b * NPIX * CIN;

    #pragma unroll 1
    for (int s = 0; s < 18; s++) {
        int k2 = s >> 1, half = s & 1;
        int ky = k2 / 3 - 1, kx = k2 % 3 - 1;

        __syncthreads();

        // async copy B hi+lo (32KB)
        {
            const char* src = (const char*)g_woffbf + (size_t)(k2 * 2 + half) * 32768;
            #pragma unroll
            for (int i = 0; i < 8; i++) {
                int e = tid + i * 256;
                uint32_t dst = sb + OB_HI + (uint32_t)e * 16;
                asm volatile("cp.async.cg.shared.global [%0], [%1], 16;"
                             :: "r"(dst), "l"(src + (size_t)e * 16) : "memory");
            }
            asm volatile("cp.async.commit_group;" ::: "memory");
        }

        // build A hi/lo: warp w -> pix rows wid*8..+7; shifted copy (zero pad)
        int y = ptile + ky;
        #pragma unroll 4
        for (int j = 0; j < 8; j++) {
            int pl = wid * 8 + j;
            int x_ = pl + kx;
            bool ok = (y >= 0) && (y < HH) && (x_ >= 0) && (x_ < WW);
            float4 a = make_float4(0.f, 0.f, 0.f, 0.f);
            if (ok) a = *(const float4*)(xb + ((size_t)(y * WW + x_)) * CIN + half * 128 + lane * 4);
            uint32_t h0 = packbf(a.x, a.y), h1 = packbf(a.z, a.w);
            uint32_t l0 = packbf(a.x - bflo(h0), a.y - bfhi(h0));
            uint32_t l1 = packbf(a.z - bflo(h1), a.w - bfhi(h1));
            uint32_t off = (uint32_t)pl * 256 + (((uint32_t)lane * 8) ^ ((uint32_t)(pl & 7) << 4));
            *(uint2*)(dsm + OA_HI + off) = make_uint2(h0, h1);
            *(uint2*)(dsm + OA_LO + off) = make_uint2(l0, l1);
        }

        asm volatile("cp.async.wait_group 0;" ::: "memory");
        __syncthreads();

        // MMA: 8 k-chunks x 2 b-groups x 3 terms (warp 16 pix x 32 oc)
        #pragma unroll 2
        for (int kc = 0; kc < 8; kc++) {
            uint32_t cb = (uint32_t)kc * 32;
            uint32_t colA = (cb + cA) ^ swz;
            uint32_t colB = (cb + cB) ^ swz;
            uint32_t aH[4], aL[4];
            uint32_t ra = aRow + colA;
            ldsm4(aH[0], aH[1], aH[2], aH[3], ra);
            ldsm4(aL[0], aL[1], aL[2], aL[3], ra + 16384);
            #pragma unroll
            for (int ng = 0; ng < 2; ng++) {
                uint32_t rb = bRow[ng] + colB;
                uint32_t bh0, bh1, bh2, bh3, bl0, bl1, bl2, bl3;
                ldsm4(bh0, bh1, bh2, bh3, rb);
                ldsm4(bl0, bl1, bl2, bl3, rb + 16384);
                mma16816(acc[2 * ng],     aH, bh0, bh1);
                mma16816(acc[2 * ng],     aH, bl0, bl1);
                mma16816(acc[2 * ng],     aL, bh0, bh1);
                mma16816(acc[2 * ng + 1], aH, bh2, bh3);
                mma16816(acc[2 * ng + 1], aH, bl2, bl3);
                mma16816(acc[2 * ng + 1], aL, bh2, bh3);
            }
        }
    }

    // epilogue: + b_off, store g_om [b][p][54]
    {
        int prow = p0 + pix0 + (lane >> 2);
        int obase = o0 + (lane & 3) * 2;
        #pragma unroll
        for (int nt = 0; nt < 4; nt++) {
            int o = obase + nt * 8;
            float* r0 = &g_om[((size_t)(b * NPIX) + prow) * 54];
            float* r1 = r0 + 8 * 54;
            if (o < 54) {
                float bo = b_off[o];
                r0[o] = acc[nt][0] + bo;
                r1[o] = acc[nt][2] + bo;
            }
            if (o + 1 < 54) {
                float bo = b_off[o + 1];
                r0[o + 1] = acc[nt][1] + bo;
                r1[o + 1] = acc[nt][3] + bo;
            }
        }
    }
}

// ---------------- kernel 4: deformable conv via mma.sync bf16x3 + BN + ReLU ----------------
// block = 256 thr (8 warps), tile = 128 pix x 256 o; warp = 64 pix x 64 o (round-10 best shape)
// NEW: B double-buffered by 64-c K-chunks (2 x 64KB), cp.async pipelined across chunks.
#define SA_HI   0          // A hi tile 32KB: 128 pix rows x 128 c bf16, 256B pitch, swizzled
#define SA_LO   32768      // A lo tile 32KB
#define SB_BASE 65536      // 2 bufs x 64KB: buf j at SB_BASE + j*65536; [hi 32KB][lo 32KB]
#define SCW     196608     // float cw[128][4]
#define SCI     198656     // int   ci[128][4]
#define SSS     200704     // float scale[256]
#define SSH     201728     // float shift[256]
#define SMEM_SZ 202752

__global__ void __launch_bounds__(256, 1) k_main_mma(
    const float* __restrict__ bconv, const float* __restrict__ gamma,
    const float* __restrict__ beta,  const float* __restrict__ rmean,
    const float* __restrict__ rvar,  float* __restrict__ out) {

    extern __shared__ char dsm[];
    uint32_t sb = smem_u32(dsm);
    int tid = threadIdx.x;
    int lane = tid & 31, wid = tid >> 5;

    int b  = blockIdx.x >> 5;
    int p0 = (blockIdx.x & 31) << 7;     // 128 pixels (2 image rows)

    int pix0 = (wid & 1) * 64;           // warp pixel sub-tile (64 pix)
    int o0   = (wid >> 1) * 64;          // warp o sub-tile (64 o)

    float* cw  = (float*)(dsm + SCW);
    int*   ci  = (int*)(dsm + SCI);
    float* sss = (float*)(dsm + SSS);
    float* ssh = (float*)(dsm + SSH);

    {   // BN fold (all 256 o)
        int o = tid;
        float sc = gamma[o] * rsqrtf(rvar[o] + 1e-5f);
        sss[o] = sc;
        ssh[o] = (bconv[o] - rmean[o]) * sc + beta[o];
    }

    int rowA = lane & 15;
    uint32_t cA   = (uint32_t)((lane >> 4) << 4);
    int rowB = (lane & 7) + ((lane >> 4) << 3);
    uint32_t cB   = (uint32_t)(((lane >> 3) & 1) << 4);
    uint32_t swz  = (uint32_t)((lane & 7) << 4);

    uint32_t aRow[4];
    #pragma unroll
    for (int mt = 0; mt < 4; mt++)
        aRow[mt] = sb + SA_HI + (uint32_t)(pix0 + mt * 16 + rowA) * 256;
    uint32_t bRowOff[4];                 // offsets within a B buffer (128B pitch)
    #pragma unroll
    for (int ng = 0; ng < 4; ng++)
        bRowOff[ng] = (uint32_t)(o0 + ng * 16 + rowB) * 128;

    float acc[4][8][4];
    #pragma unroll
    for (int mt = 0; mt < 4; mt++)
        #pragma unroll
        for (int nt = 0; nt < 8; nt++)
            #pragma unroll
            for (int q = 0; q < 4; q++) acc[mt][nt][q] = 0.f;

    const float* xb  = g_xt + (size_t)b * NPIX * CIN;
    const float* omb = g_om + (size_t)b * NPIX * 54;

    // prefetch chunks 0 and 1 of tap 0 into buffers 0 and 1 (one commit group each)
    #pragma unroll
    for (int pre = 0; pre < 2; pre++) {
        const char* src = (const char*)g_wbf + (size_t)pre * 65536;
        #pragma unroll
        for (int i = 0; i < 16; i++) {
            int e = tid + i * 256;
            uint32_t dst = sb + SB_BASE + (uint32_t)pre * 65536 + (uint32_t)e * 16;
            asm volatile("cp.async.cg.shared.global [%0], [%1], 16;"
                         :: "r"(dst), "l"(src + (size_t)e * 16) : "memory");
        }
        asm volatile("cp.async.commit_group;" ::: "memory");
    }

    #pragma unroll 1
    for (int s = 0; s < 36; s++) {
        int tap = s >> 1, chunk = s & 1, buf = s & 1;

        if (chunk == 0) {
            int g = tap / KK2, k2 = tap % KK2;
            // offsets / bilinear corner weights for the 128 pixels
            if (tid < 128) {
                int p = p0 + tid;
                int prow = p >> 6, wx = p & 63;
                const float* om = &omb[(size_t)p * 54 + tap];
                float offy = om[0], offx = om[18], mraw = om[36];
                float mask = 1.f / (1.f + expf(-mraw));
                float py = (float)(prow + k2 / 3 - 1) + offy;
                float px = (float)(wx   + k2 % 3 - 1) + offx;
                float fy = floorf(py), fx = floorf(px);
                float ly = py - fy, lx = px - fx;
                int y0 = (int)fy, x0 = (int)fx;
                float wgt[4] = { (1.f - ly) * (1.f - lx), (1.f - ly) * lx,
                                 ly * (1.f - lx),         ly * lx };
                #pragma unroll
                for (int cr = 0; cr < 4; cr++) {
                    int yy = y0 + (cr >> 1), xx = x0 + (cr & 1);
                    bool v = (yy >= 0) && (yy < HH) && (xx >= 0) && (xx < WW);
                    cw[tid * 4 + cr] = v ? wgt[cr] * mask : 0.f;
                    ci[tid * 4 + cr] = v ? ((yy * WW + xx) * CIN + g * CG) : 0;
                }
            }
            __syncthreads();

            // build A hi/lo tiles: warp w -> pix rows wid*16 .. +15
            #pragma unroll 4
            for (int j = 0; j < 16; j++) {
                int pl = wid * 16 + j;
                float w0 = cw[pl * 4 + 0], w1 = cw[pl * 4 + 1];
                float w2 = cw[pl * 4 + 2], w3 = cw[pl * 4 + 3];
                int   i0 = ci[pl * 4 + 0], i1 = ci[pl * 4 + 1];
                int   i2 = ci[pl * 4 + 2], i3 = ci[pl * 4 + 3];
                int c4 = lane * 4;
                float4 a0 = *(const float4*)(xb + i0 + c4);
                float4 a1 = *(const float4*)(xb + i1 + c4);
                float4 a2 = *(const float4*)(xb + i2 + c4);
                float4 a3 = *(const float4*)(xb + i3 + c4);
                float v0 = w0 * a0.x + w1 * a1.x + w2 * a2.x + w3 * a3.x;
                float v1 = w0 * a0.y + w1 * a1.y + w2 * a2.y + w3 * a3.y;
                float v2 = w0 * a0.z + w1 * a1.z + w2 * a2.z + w3 * a3.z;
                float v3 = w0 * a0.w + w1 * a1.w + w2 * a2.w + w3 * a3.w;
                uint32_t h0 = packbf(v0, v1), h1 = packbf(v2, v3);
                uint32_t l0 = packbf(v0 - bflo(h0), v1 - bfhi(h0));
                uint32_t l1 = packbf(v2 - bflo(h1), v3 - bfhi(h1));
                uint32_t off = (uint32_t)pl * 256 + (((uint32_t)lane * 8) ^ ((uint32_t)(pl & 7) << 4));
                *(uint2*)(dsm + SA_HI + off) = make_uint2(h0, h1);
                *(uint2*)(dsm + SA_LO + off) = make_uint2(l0, l1);
            }
        }

        // wait for this chunk's B buffer (leave the next prefetch in flight)
        if (s == 35) asm volatile("cp.async.wait_group 0;" ::: "memory");
        else         asm volatile("cp.async.wait_group 1;" ::: "memory");
        __syncthreads();

        // MMA: 4 local k-chunks x 4 m-tiles x 4 b-groups x 3 terms
        uint32_t bBase = sb + SB_BASE + (uint32_t)buf * 65536;
        uint32_t aChunk = (uint32_t)chunk * 128;
        #pragma unroll
        for (int kcl = 0; kcl < 4; kcl++) {
            uint32_t colA = (aChunk + (uint32_t)kcl * 32 + cA) ^ swz;
            uint32_t colB = ((uint32_t)kcl * 32 + cB) ^ swz;
            uint32_t aH[4][4], aL[4][4];
            #pragma unroll
            for (int mt = 0; mt < 4; mt++) {
                uint32_t ra = aRow[mt] + colA;
                ldsm4(aH[mt][0], aH[mt][1], aH[mt][2], aH[mt][3], ra);
                ldsm4(aL[mt][0], aL[mt][1], aL[mt][2], aL[mt][3], ra + 32768);
            }
            #pragma unroll
            for (int ng = 0; ng < 4; ng++) {
                uint32_t rb = bBase + bRowOff[ng] + colB;
                uint32_t bh0, bh1, bh2, bh3, bl0, bl1, bl2, bl3;
                ldsm4(bh0, bh1, bh2, bh3, rb);
                ldsm4(bl0, bl1, bl2, bl3, rb + 32768);
                #pragma unroll
                for (int mt = 0; mt < 4; mt++) {
                    mma16816(acc[mt][2 * ng],     aH[mt], bh0, bh1);
                    mma16816(acc[mt][2 * ng],     aH[mt], bl0, bl1);
                    mma16816(acc[mt][2 * ng],     aL[mt], bh0, bh1);
                    mma16816(acc[mt][2 * ng + 1], aH[mt], bh2, bh3);
                    mma16816(acc[mt][2 * ng + 1], aH[mt], bl2, bl3);
                    mma16816(acc[mt][2 * ng + 1], aL[mt], bh2, bh3);
                }
            }
        }
        __syncthreads();   // all warps done reading buf (and A, if tap boundary next)

        // prefetch chunk s+2 into this buffer
        if (s + 2 < 36) {
            int s2 = s + 2;
            const char* src = (const char*)g_wbf + (size_t)(s2 >> 1) * 131072 + (size_t)(s2 & 1) * 65536;
            #pragma unroll
            for (int i = 0; i < 16; i++) {
                int e = tid + i * 256;
                uint32_t dst = sb + SB_BASE + (uint32_t)buf * 65536 + (uint32_t)e * 16;
                asm volatile("cp.async.cg.shared.global [%0], [%1], 16;"
                             :: "r"(dst), "l"(src + (size_t)e * 16) : "memory");
            }
            asm volatile("cp.async.commit_group;" ::: "memory");
        }
    }

    // epilogue: BN + ReLU, direct stores
    {
        int prow = p0 + pix0 + (lane >> 2);
        int obase = o0 + (lane & 3) * 2;
        #pragma unroll
        for (int mt = 0; mt < 4; mt++) {
            #pragma unroll
            for (int nt = 0; nt < 8; nt++) {
                int o = obase + nt * 8;
                int p = prow + mt * 16;
                float s0 = sss[o],     h0 = ssh[o];
                float s1 = sss[o + 1], h1 = ssh[o + 1];
                float* base0 = out + ((size_t)(b * COUT + o)) * NPIX;
                float* base1 = out + ((size_t)(b * COUT + o + 1)) * NPIX;
                base0[p]     = fmaxf(acc[mt][nt][0] * s0 + h0, 0.f);
                base1[p]     = fmaxf(acc[mt][nt][1] * s1 + h1, 0.f);
                base0[p + 8] = fmaxf(acc[mt][nt][2] * s0 + h0, 0.f);
                base1[p + 8] = fmaxf(acc[mt][nt][3] * s1 + h1, 0.f);
            }
        }
    }
}

// ---------------- launch ----------------
extern "C" void kernel_launch(void* const* d_in, const int* in_sizes, int n_in,
                              void* d_out, int out_size) {
    const float* x     = (const float*)d_in[0];
    const float* w_off = (const float*)d_in[1];
    const float* b_off = (const float*)d_in[2];
    const float* w     = (const float*)d_in[3];
    const float* bconv = (const float*)d_in[4];
    const float* gamma = (const float*)d_in[5];
    const float* beta  = (const float*)d_in[6];
    const float* rmean = (const float*)d_in[7];
    const float* rvar  = (const float*)d_in[8];
    float* out = (float*)d_out;

    cudaFuncSetAttribute(k_main_mma,   cudaFuncAttributeMaxDynamicSharedMemorySize, SMEM_SZ);
    cudaFuncSetAttribute(k_offset_mma, cudaFuncAttributeMaxDynamicSharedMemorySize, OSMEM_SZ);

    k_transpose_x<<<dim3(NPIX / 32, CIN / 32, BB), dim3(32, 8)>>>(x);
    k_prep_wbf<<<(NTAP * 256 * 64 + 255) / 256, 256>>>(w);
    k_prep_woffbf<<<(KK2 * 2 * 64 * 64 + 255) / 256, 256>>>(w_off);
    k_offset_mma<<<BB * 64, 256, OSMEM_SZ>>>(b_off);
    k_main_mma<<<BB * 32, 256, SMEM_SZ>>>(bconv, gamma, beta, rmean, rvar, out);
}

// round 17
// speedup vs baseline: 1.4835x; 1.4835x over previous
#include <cuda_runtime.h>
#include <math.h>
#include <stdint.h>

#define CIN  256
#define COUT 256
#define HH   64
#define WW   64
#define BB   4
#define DGRP 2
#define CG   128
#define KK2  9
#define NTAP 18
#define NPIX 4096   // 64*64

// ---------------- scratch (device globals; no allocations allowed) ----------------
__device__ float g_xt[BB * NPIX * CIN];                       // x -> [B][H*W][C]
__device__ float g_om[BB * NPIX * 54];                        // offset-conv out [b][p][54]
__device__ __align__(128) unsigned char g_wbf[NTAP * 131072]; // main w: per tap [hi 64KB][lo 64KB], swizzled
__device__ __align__(128) unsigned char g_woffbf[KK2 * 2 * 32768]; // w_off: per (k2,half) [hi 16KB][lo 16KB]

// ---------------- bf16 helpers ----------------
// packbf(vlo, vhi): vlo -> low 16 bits, vhi -> high 16 bits
static __device__ __forceinline__ uint32_t packbf(float vlo, float vhi) {
    uint32_t r;
    asm("cvt.rn.bf16x2.f32 %0, %1, %2;" : "=r"(r) : "f"(vhi), "f"(vlo));
    return r;
}
static __device__ __forceinline__ float bflo(uint32_t w) { return __uint_as_float(w << 16); }
static __device__ __forceinline__ float bfhi(uint32_t w) { return __uint_as_float(w & 0xffff0000u); }

static __device__ __forceinline__ uint32_t smem_u32(const void* p) {
    uint32_t a;
    asm("{ .reg .u64 t; cvta.to.shared.u64 t, %1; cvt.u32.u64 %0, t; }" : "=r"(a) : "l"(p));
    return a;
}

// ---------------- mma.sync / ldmatrix (base-arch PTX, HMMA pipe) ----------------
static __device__ __forceinline__ void ldsm4(uint32_t& r0, uint32_t& r1,
                                             uint32_t& r2, uint32_t& r3, uint32_t a) {
    asm volatile("ldmatrix.sync.aligned.m8n8.x4.shared.b16 {%0,%1,%2,%3}, [%4];"
                 : "=r"(r0), "=r"(r1), "=r"(r2), "=r"(r3) : "r"(a));
}
static __device__ __forceinline__ void mma16816(float* c, const uint32_t* a,
                                                uint32_t b0, uint32_t b1) {
    asm volatile(
        "mma.sync.aligned.m16n8k16.row.col.f32.bf16.bf16.f32 "
        "{%0,%1,%2,%3}, {%4,%5,%6,%7}, {%8,%9}, {%0,%1,%2,%3};"
        : "+f"(c[0]), "+f"(c[1]), "+f"(c[2]), "+f"(c[3])
        : "r"(a[0]), "r"(a[1]), "r"(a[2]), "r"(a[3]), "r"(b0), "r"(b1));
}

// smem tile addressing: rows of 128 bf16 (256B pitch), 16B-unit XOR swizzle by (row&7)
// byte(row, cbyte) = row*256 + (cbyte ^ ((row&7)<<4))

// ---------------- kernel 0: x [B,C,H,W] -> g_xt [B,HW,C] ----------------
__global__ void k_transpose_x(const float* __restrict__ x) {
    __shared__ float tile[32][33];
    int b  = blockIdx.z;
    int p0 = blockIdx.x * 32;
    int c0 = blockIdx.y * 32;
    #pragma unroll
    for (int k = 0; k < 32; k += 8)
        tile[threadIdx.y + k][threadIdx.x] = x[(b * CIN + c0 + threadIdx.y + k) * NPIX + p0 + threadIdx.x];
    __syncthreads();
    #pragma unroll
    for (int k = 0; k < 32; k += 8)
        g_xt[(b * NPIX + p0 + threadIdx.y + k) * CIN + c0 + threadIdx.x] = tile[threadIdx.x][threadIdx.y + k];
}

// ---------------- kernel 1: w -> g_wbf (bf16 hi/lo, swizzled [o row][c] tiles) ----------------
__global__ void k_prep_wbf(const float* __restrict__ w) {
    int tid = blockIdx.x * blockDim.x + threadIdx.x;
    if (tid >= NTAP * 256 * 64) return;
    int cp  = tid & 63;             // c pair index: c0 = 2*cp
    int o   = (tid >> 6) & 255;
    int tap = tid >> 14;
    int g = tap / KK2, k2 = tap % KK2;
    int c0 = cp * 2;
    float f0 = w[((size_t)o * CIN + g * CG + c0) * KK2 + k2];
    float f1 = w[((size_t)o * CIN + g * CG + c0 + 1) * KK2 + k2];
    uint32_t hiw = packbf(f0, f1);
    float r0 = f0 - bflo(hiw);
    float r1 = f1 - bfhi(hiw);
    uint32_t low = packbf(r0, r1);
    uint32_t sw = (uint32_t)o * 256 + (((uint32_t)c0 * 2) ^ (((uint32_t)(o & 7)) << 4));
    size_t base = (size_t)tap * 131072;
    *(uint32_t*)(g_wbf + base + sw)         = hiw;
    *(uint32_t*)(g_wbf + base + 65536 + sw) = low;
}

// ---------------- kernel 2: w_off -> g_woffbf bf16 hi/lo tiles [k2][half]: 64 oc x 128 c ----------------
__global__ void k_prep_woffbf(const float* __restrict__ w_off) {
    int tid = blockIdx.x * blockDim.x + threadIdx.x;
    if (tid >= KK2 * 2 * 64 * 64) return;
    int cp   = tid & 63;            // c pair: c0 = 2*cp within half
    int o    = (tid >> 6) & 63;     // oc row (pad >=54 with 0)
    int half = (tid >> 12) & 1;
    int k2   = tid >> 13;           // 0..8
    int c0 = cp * 2;
    float f0 = 0.f, f1 = 0.f;
    if (o < 54) {
        f0 = w_off[((size_t)o * CIN + half * 128 + c0) * KK2 + k2];
        f1 = w_off[((size_t)o * CIN + half * 128 + c0 + 1) * KK2 + k2];
    }
    uint32_t hiw = packbf(f0, f1);
    float r0 = f0 - bflo(hiw);
    float r1 = f1 - bfhi(hiw);
    uint32_t low = packbf(r0, r1);
    uint32_t sw = (uint32_t)o * 256 + (((uint32_t)c0 * 2) ^ (((uint32_t)(o & 7)) << 4));
    size_t base = (size_t)(k2 * 2 + half) * 32768;
    *(uint32_t*)(g_woffbf + base + sw)         = hiw;
    *(uint32_t*)(g_woffbf + base + 16384 + sw) = low;
}

// ---------------- kernel 3: offset conv via mma.sync bf16x3 (round-14 best shape) ----------------
// block = 256 thr (8 warps), tile = 64 pix x 64 oc(pad); warp = 16 pix x 32 oc
// smem: A hi 16KB | A lo 16KB | B hi 16KB | B lo 16KB = 64KB  -> 2 blocks/SM
#define OA_HI 0
#define OA_LO 16384
#define OB_HI 32768
#define OB_LO 49152
#define OSMEM_SZ 65536

__global__ void __launch_bounds__(256, 2) k_offset_mma(const float* __restrict__ b_off) {
    extern __shared__ char dsm[];
    uint32_t sb = smem_u32(dsm);
    int tid = threadIdx.x;
    int lane = tid & 31, wid = tid >> 5;

    int b     = blockIdx.x >> 6;
    int ptile = blockIdx.x & 63;
    int p0    = ptile << 6;          // 64 pixels = one image row

    int pix0 = (wid & 3) * 16;       // warp pixel sub-tile
    int o0   = (wid >> 2) * 32;      // warp oc sub-tile

    // ldmatrix lane geometry
    int rowA = lane & 15;
    uint32_t cA  = (uint32_t)((lane >> 4) << 4);
    int rowB = (lane & 7) + ((lane >> 4) << 3);
    uint32_t cB  = (uint32_t)(((lane >> 3) & 1) << 4);
    uint32_t swz = (uint32_t)((lane & 7) << 4);

    uint32_t aRow = sb + OA_HI + (uint32_t)(pix0 + rowA) * 256;
    uint32_t bRow[2];
    #pragma unroll
    for (int ng = 0; ng < 2; ng++)
        bRow[ng] = sb + OB_HI + (uint32_t)(o0 + ng * 16 + rowB) * 256;

    float acc[4][4];
    #pragma unroll
    for (int nt = 0; nt < 4; nt++)
        #pragma unroll
        for (int q = 0; q < 4; q++) acc[nt][q] = 0.f;

    const float* xb = g_xt + (size_t)b * NPIX * CIN;

    #pragma unroll 1
    for (int s = 0; s < 18; s++) {
        int k2 = s >> 1, half = s & 1;
        int ky = k2 / 3 - 1, kx = k2 % 3 - 1;

        __syncthreads();

        // async copy B hi+lo (32KB)
        {
            const char* src = (const char*)g_woffbf + (size_t)(k2 * 2 + half) * 32768;
            #pragma unroll
            for (int i = 0; i < 8; i++) {
                int e = tid + i * 256;
                uint32_t dst = sb + OB_HI + (uint32_t)e * 16;
                asm volatile("cp.async.cg.shared.global [%0], [%1], 16;"
                             :: "r"(dst), "l"(src + (size_t)e * 16) : "memory");
            }
            asm volatile("cp.async.commit_group;" ::: "memory");
        }

        // build A hi/lo: warp w -> pix rows wid*8..+7; shifted copy (zero pad)
        int y = ptile + ky;
        #pragma unroll 4
        for (int j = 0; j < 8; j++) {
            int pl = wid * 8 + j;
            int x_ = pl + kx;
            bool ok = (y >= 0) && (y < HH) && (x_ >= 0) && (x_ < WW);
            float4 a = make_float4(0.f, 0.f, 0.f, 0.f);
            if (ok) a = *(const float4*)(xb + ((size_t)(y * WW + x_)) * CIN + half * 128 + lane * 4);
            uint32_t h0 = packbf(a.x, a.y), h1 = packbf(a.z, a.w);
            uint32_t l0 = packbf(a.x - bflo(h0), a.y - bfhi(h0));
            uint32_t l1 = packbf(a.z - bflo(h1), a.w - bfhi(h1));
            uint32_t off = (uint32_t)pl * 256 + (((uint32_t)lane * 8) ^ ((uint32_t)(pl & 7) << 4));
            *(uint2*)(dsm + OA_HI + off) = make_uint2(h0, h1);
            *(uint2*)(dsm + OA_LO + off) = make_uint2(l0, l1);
        }

        asm volatile("cp.async.wait_group 0;" ::: "memory");
        __syncthreads();

        // MMA: 8 k-chunks x 2 b-groups x 3 terms (warp 16 pix x 32 oc)
        #pragma unroll 2
        for (int kc = 0; kc < 8; kc++) {
            uint32_t cb = (uint32_t)kc * 32;
            uint32_t colA = (cb + cA) ^ swz;
            uint32_t colB = (cb + cB) ^ swz;
            uint32_t aH[4], aL[4];
            uint32_t ra = aRow + colA;
            ldsm4(aH[0], aH[1], aH[2], aH[3], ra);
            ldsm4(aL[0], aL[1], aL[2], aL[3], ra + 16384);
            #pragma unroll
            for (int ng = 0; ng < 2; ng++) {
                uint32_t rb = bRow[ng] + colB;
                uint32_t bh0, bh1, bh2, bh3, bl0, bl1, bl2, bl3;
                ldsm4(bh0, bh1, bh2, bh3, rb);
                ldsm4(bl0, bl1, bl2, bl3, rb + 16384);
                mma16816(acc[2 * ng],     aH, bh0, bh1);
                mma16816(acc[2 * ng],     aH, bl0, bl1);
                mma16816(acc[2 * ng],     aL, bh0, bh1);
                mma16816(acc[2 * ng + 1], aH, bh2, bh3);
                mma16816(acc[2 * ng + 1], aH, bl2, bl3);
                mma16816(acc[2 * ng + 1], aL, bh2, bh3);
            }
        }
    }

    // epilogue: + b_off, store g_om [b][p][54]
    {
        int prow = p0 + pix0 + (lane >> 2);
        int obase = o0 + (lane & 3) * 2;
        #pragma unroll
        for (int nt = 0; nt < 4; nt++) {
            int o = obase + nt * 8;
            float* r0 = &g_om[((size_t)(b * NPIX) + prow) * 54];
            float* r1 = r0 + 8 * 54;
            if (o < 54) {
                float bo = b_off[o];
                r0[o] = acc[nt][0] + bo;
                r1[o] = acc[nt][2] + bo;
            }
            if (o + 1 < 54) {
                float bo = b_off[o + 1];
                r0[o + 1] = acc[nt][1] + bo;
                r1[o + 1] = acc[nt][3] + bo;
            }
        }
    }
}

// ---------------- kernel 4: deformable conv via mma.sync bf16x3 + BN + ReLU (round-12 best shape) ----------------
// block = 256 thr (8 warps), tile = 128 pix x 256 o; warp tile = 64 pix x 64 o
#define SA_HI   0          // A hi tile 32KB: 128 pix rows x 128 c bf16, swizzled
#define SA_LO   32768      // A lo tile 32KB
#define SB_HI   65536      // B hi tile 64KB: 256 o rows x 128 c bf16, swizzled
#define SB_LO   131072     // B lo tile 64KB
#define SCW     196608     // float cw[128][4]
#define SCI     198656     // int   ci[128][4]
#define SSS     200704     // float scale[256]
#define SSH     201728     // float shift[256]
#define SMEM_SZ 202752

__global__ void __launch_bounds__(256, 1) k_main_mma(
    const float* __restrict__ bconv, const float* __restrict__ gamma,
    const float* __restrict__ beta,  const float* __restrict__ rmean,
    const float* __restrict__ rvar,  float* __restrict__ out) {

    extern __shared__ char dsm[];
    uint32_t sb = smem_u32(dsm);
    int tid = threadIdx.x;
    int lane = tid & 31, wid = tid >> 5;

    int b  = blockIdx.x >> 5;
    int p0 = (blockIdx.x & 31) << 7;     // 128 pixels (2 image rows)

    // warp tile origin
    int pix0 = (wid & 1) * 64;
    int o0   = (wid >> 1) * 64;

    float* cw  = (float*)(dsm + SCW);
    int*   ci  = (int*)(dsm + SCI);
    float* sss = (float*)(dsm + SSS);
    float* ssh = (float*)(dsm + SSH);

    {   // BN fold
        int o = tid;
        float sc = gamma[o] * rsqrtf(rvar[o] + 1e-5f);
        sss[o] = sc;
        ssh[o] = (bconv[o] - rmean[o]) * sc + beta[o];
    }

    int rowA = lane & 15;
    uint32_t cA   = (uint32_t)((lane >> 4) << 4);
    int rowB = (lane & 7) + ((lane >> 4) << 3);
    uint32_t cB   = (uint32_t)(((lane >> 3) & 1) << 4);
    uint32_t swz  = (uint32_t)((lane & 7) << 4);

    uint32_t aRow[4], bRow[4];
    #pragma unroll
    for (int mt = 0; mt < 4; mt++)
        aRow[mt] = sb + SA_HI + (uint32_t)(pix0 + mt * 16 + rowA) * 256;
    #pragma unroll
    for (int ng = 0; ng < 4; ng++)
        bRow[ng] = sb + SB_HI + (uint32_t)(o0 + ng * 16 + rowB) * 256;

    float acc[4][8][4];
    #pragma unroll
    for (int mt = 0; mt < 4; mt++)
        #pragma unroll
        for (int nt = 0; nt < 8; nt++)
            #pragma unroll
            for (int q = 0; q < 4; q++) acc[mt][nt][q] = 0.f;

    const float* xb  = g_xt + (size_t)b * NPIX * CIN;
    const float* omb = g_om + (size_t)b * NPIX * 54;

    #pragma unroll 1
    for (int tap = 0; tap < NTAP; tap++) {
        int g = tap / KK2, k2 = tap % KK2;

        __syncthreads();   // everyone done reading previous A/B tiles

        // async flat copy of this tap's pre-swizzled B hi+lo (128KB)
        {
            const char* src = (const char*)g_wbf + (size_t)tap * 131072;
            #pragma unroll 4
            for (int i = tid; i < 8192; i += 256) {
                uint32_t dst = sb + SB_HI + (uint32_t)i * 16;
                asm volatile("cp.async.cg.shared.global [%0], [%1], 16;"
                             :: "r"(dst), "l"(src + (size_t)i * 16) : "memory");
            }
            asm volatile("cp.async.commit_group;" ::: "memory");
        }

        // offsets / bilinear corner weights for the 128 pixels
        if (tid < 128) {
            int p = p0 + tid;
            int prow = p >> 6, wx = p & 63;
            const float* om = &omb[(size_t)p * 54 + tap];
            float offy = om[0], offx = om[18], mraw = om[36];
            float mask = 1.f / (1.f + expf(-mraw));
            float py = (float)(prow + k2 / 3 - 1) + offy;
            float px = (float)(wx   + k2 % 3 - 1) + offx;
            float fy = floorf(py), fx = floorf(px);
            float ly = py - fy, lx = px - fx;
            int y0 = (int)fy, x0 = (int)fx;
            float wgt[4] = { (1.f - ly) * (1.f - lx), (1.f - ly) * lx,
                             ly * (1.f - lx),         ly * lx };
            #pragma unroll
            for (int cr = 0; cr < 4; cr++) {
                int yy = y0 + (cr >> 1), xx = x0 + (cr & 1);
                bool v = (yy >= 0) && (yy < HH) && (xx >= 0) && (xx < WW);
                cw[tid * 4 + cr] = v ? wgt[cr] * mask : 0.f;
                ci[tid * 4 + cr] = v ? ((yy * WW + xx) * CIN + g * CG) : 0;
            }
        }
        __syncthreads();

        // build A hi/lo tiles: warp w -> pix rows wid*16 .. +15; lane covers 4 c via float4
        #pragma unroll 4
        for (int j = 0; j < 16; j++) {
            int pl = wid * 16 + j;
            float w0 = cw[pl * 4 + 0], w1 = cw[pl * 4 + 1];
            float w2 = cw[pl * 4 + 2], w3 = cw[pl * 4 + 3];
            int   i0 = ci[pl * 4 + 0], i1 = ci[pl * 4 + 1];
            int   i2 = ci[pl * 4 + 2], i3 = ci[pl * 4 + 3];
            int c4 = lane * 4;
            float4 a0 = *(const float4*)(xb + i0 + c4);
            float4 a1 = *(const float4*)(xb + i1 + c4);
            float4 a2 = *(const float4*)(xb + i2 + c4);
            float4 a3 = *(const float4*)(xb + i3 + c4);
            float v0 = w0 * a0.x + w1 * a1.x + w2 * a2.x + w3 * a3.x;
            float v1 = w0 * a0.y + w1 * a1.y + w2 * a2.y + w3 * a3.y;
            float v2 = w0 * a0.z + w1 * a1.z + w2 * a2.z + w3 * a3.z;
            float v3 = w0 * a0.w + w1 * a1.w + w2 * a2.w + w3 * a3.w;
            uint32_t h0 = packbf(v0, v1), h1 = packbf(v2, v3);
            uint32_t l0 = packbf(v0 - bflo(h0), v1 - bfhi(h0));
            uint32_t l1 = packbf(v2 - bflo(h1), v3 - bfhi(h1));
            uint32_t off = (uint32_t)pl * 256 + (((uint32_t)lane * 8) ^ ((uint32_t)(pl & 7) << 4));
            *(uint2*)(dsm + SA_HI + off) = make_uint2(h0, h1);
            *(uint2*)(dsm + SA_LO + off) = make_uint2(l0, l1);
        }

        asm volatile("cp.async.wait_group 0;" ::: "memory");
        __syncthreads();

        // MMA phase: 8 k-chunks x (4 m-tiles x 8 n-tiles) x 3 precision terms
        #pragma unroll 2
        for (int kc = 0; kc < 8; kc++) {
            uint32_t cb = (uint32_t)kc * 32;
            uint32_t colA = (cb + cA) ^ swz;
            uint32_t colB = (cb + cB) ^ swz;
            uint32_t aH[4][4], aL[4][4];
            #pragma unroll
            for (int mt = 0; mt < 4; mt++) {
                uint32_t ra = aRow[mt] + colA;
                ldsm4(aH[mt][0], aH[mt][1], aH[mt][2], aH[mt][3], ra);
                ldsm4(aL[mt][0], aL[mt][1], aL[mt][2], aL[mt][3], ra + 32768);
            }
            #pragma unroll
            for (int ng = 0; ng < 4; ng++) {
                uint32_t rb = bRow[ng] + colB;
                uint32_t bh0, bh1, bh2, bh3, bl0, bl1, bl2, bl3;
                ldsm4(bh0, bh1, bh2, bh3, rb);
                ldsm4(bl0, bl1, bl2, bl3, rb + 65536);
                #pragma unroll
                for (int mt = 0; mt < 4; mt++) {
                    mma16816(acc[mt][2 * ng],     aH[mt], bh0, bh1);
                    mma16816(acc[mt][2 * ng],     aH[mt], bl0, bl1);
                    mma16816(acc[mt][2 * ng],     aL[mt], bh0, bh1);
                    mma16816(acc[mt][2 * ng + 1], aH[mt], bh2, bh3);
                    mma16816(acc[mt][2 * ng + 1], aH[mt], bl2, bl3);
                    mma16816(acc[mt][2 * ng + 1], aL[mt], bh2, bh3);
                }
            }
        }
    }

    // epilogue: BN + ReLU, direct stores (8-lane x 4B coalesced chunks)
    {
        int prow = p0 + pix0 + (lane >> 2);
        int obase = o0 + (lane & 3) * 2;
        #pragma unroll
        for (int mt = 0; mt < 4; mt++) {
            #pragma unroll
            for (int nt = 0; nt < 8; nt++) {
                int o = obase + nt * 8;
                int p = prow + mt * 16;
                float s0 = sss[o],     h0 = ssh[o];
                float s1 = sss[o + 1], h1 = ssh[o + 1];
                float* base0 = out + ((size_t)(b * COUT + o)) * NPIX;
                float* base1 = out + ((size_t)(b * COUT + o + 1)) * NPIX;
                base0[p]     = fmaxf(acc[mt][nt][0] * s0 + h0, 0.f);
                base1[p]     = fmaxf(acc[mt][nt][1] * s1 + h1, 0.f);
                base0[p + 8] = fmaxf(acc[mt][nt][2] * s0 + h0, 0.f);
                base1[p + 8] = fmaxf(acc[mt][nt][3] * s1 + h1, 0.f);
            }
        }
    }
}

// ---------------- launch ----------------
extern "C" void kernel_launch(void* const* d_in, const int* in_sizes, int n_in,
                              void* d_out, int out_size) {
    const float* x     = (const float*)d_in[0];
    const float* w_off = (const float*)d_in[1];
    const float* b_off = (const float*)d_in[2];
    const float* w     = (const float*)d_in[3];
    const float* bconv = (const float*)d_in[4];
    const float* gamma = (const float*)d_in[5];
    const float* beta  = (const float*)d_in[6];
    const float* rmean = (const float*)d_in[7];
    const float* rvar  = (const float*)d_in[8];
    float* out = (float*)d_out;

    cudaFuncSetAttribute(k_main_mma,   cudaFuncAttributeMaxDynamicSharedMemorySize, SMEM_SZ);
    cudaFuncSetAttribute(k_offset_mma, cudaFuncAttributeMaxDynamicSharedMemorySize, OSMEM_SZ);

    k_transpose_x<<<dim3(NPIX / 32, CIN / 32, BB), dim3(32, 8)>>>(x);
    k_prep_wbf<<<(NTAP * 256 * 64 + 255) / 256, 256>>>(w);
    k_prep_woffbf<<<(KK2 * 2 * 64 * 64 + 255) / 256, 256>>>(w_off);
    k_offset_mma<<<BB * 64, 256, OSMEM_SZ>>>(b_off);
    k_main_mma<<<BB * 32, 256, SMEM_SZ>>>(bconv, gamma, beta, rmean, rvar, out);
}